// round 6
// baseline (speedup 1.0000x reference)
#include <cuda_runtime.h>
#include <math.h>
#include <stdint.h>

#define NG 1000

__device__ __align__(16) uint32_t g_h1h[(size_t)NG * 128 * 256];  // [g][m][n/2] bf16-hi pairs
__device__ __align__(16) uint32_t g_h1l[(size_t)NG * 128 * 256];  // bf16-lo pairs
__device__ float g_part[(size_t)NG * 2 * 128];

#define STAGE_BYTES 98304          // Ah 16K | Al 16K | Bh 32K | Bl 32K
#define SM_BYTES (8192 + 2 * STAGE_BYTES)   // 204800

__device__ __forceinline__ uint32_t smem_u32(const void* p){
    uint32_t a;
    asm("{ .reg .u64 t; cvta.to.shared.u64 t, %1; cvt.u32.u64 %0, t; }" : "=r"(a) : "l"(p));
    return a;
}
__device__ __forceinline__ uint32_t sw(uint32_t x){ return x ^ ((x >> 3) & 0x70u); }

__device__ __forceinline__ void split2(float f0, float f1, uint32_t& hp, uint32_t& lp){
    asm("cvt.rn.bf16x2.f32 %0, %1, %2;" : "=r"(hp) : "f"(f1), "f"(f0));
    float h1f = __uint_as_float(hp & 0xFFFF0000u);
    float h0f = __uint_as_float(hp << 16);
    asm("cvt.rn.bf16x2.f32 %0, %1, %2;" : "=r"(lp) : "f"(f1 - h1f), "f"(f0 - h0f));
}
__device__ __forceinline__ float gelu(float v){
    return 0.5f * v * (1.0f + erff(v * 0.70710678118654752440f));
}
__device__ __forceinline__ void ldsm4(uint32_t* r, uint32_t a){
    asm volatile("ldmatrix.sync.aligned.m8n8.x4.shared.b16 {%0,%1,%2,%3}, [%4];"
      : "=r"(r[0]), "=r"(r[1]), "=r"(r[2]), "=r"(r[3]) : "r"(a));
}
__device__ __forceinline__ void mmabf(float* c, const uint32_t* a, uint32_t b0, uint32_t b1){
    asm volatile("mma.sync.aligned.m16n8k16.row.col.f32.bf16.bf16.f32 "
      "{%0,%1,%2,%3},{%4,%5,%6,%7},{%8,%9},{%0,%1,%2,%3};"
      : "+f"(c[0]), "+f"(c[1]), "+f"(c[2]), "+f"(c[3])
      : "r"(a[0]), "r"(a[1]), "r"(a[2]), "r"(a[3]), "r"(b0), "r"(b1));
}
#define CP16(d,s)  asm volatile("cp.async.cg.shared.global [%0], [%1], 16;" :: "r"(d), "l"(s) : "memory")
#define CPCOMMIT() asm volatile("cp.async.commit_group;" ::: "memory")
#define CPWAIT0()  asm volatile("cp.async.wait_group 0;" ::: "memory")

struct Frag { uint32_t offA, mA, offB, mB, ksel; };

__device__ __forceinline__ Frag mk_frag(int lane, int wm, int wn){
    Frag f;
    uint32_t rA = wm * 64 + (lane & 7) + ((lane >> 3) & 1) * 8;
    uint32_t rB = wn * 32 + (lane & 7) + ((lane >> 3) & 1) * 8;
    f.ksel = ((lane >> 4) & 1) * 16;
    f.mA = (rA & 7) << 4;  f.mB = (rB & 7) << 4;
    f.offA = rA * 128;     f.offB = rB * 128;
    return f;
}

// one K=64 tile. A planes [128m][64k] (hi@st, lo@st+16K); B planes [256n][64k] (hi@st+32K, lo@st+64K)
__device__ __forceinline__ void mma_ktile(uint32_t st, const Frag& f, float c[4][4][4])
{
    uint32_t Ah = st, Al = st + 16384, Bh = st + 32768, Bl = st + 65536;
#pragma unroll
    for (int ks = 0; ks < 4; ks++){
        uint32_t ka = ks * 32 + f.ksel;
        uint32_t ao = f.offA + (ka ^ f.mA);
        uint32_t bo = f.offB + (ka ^ f.mB);
        uint32_t ah[4][4], al[4][4], bh[2][4], bl[2][4];
#pragma unroll
        for (int i = 0; i < 4; i++){ ldsm4(ah[i], Ah + ao + i*2048u); ldsm4(al[i], Al + ao + i*2048u); }
#pragma unroll
        for (int j = 0; j < 2; j++){ ldsm4(bh[j], Bh + bo + j*2048u); ldsm4(bl[j], Bl + bo + j*2048u); }
#pragma unroll
        for (int i = 0; i < 4; i++)
#pragma unroll
        for (int jt = 0; jt < 4; jt++){
            int j = jt >> 1, s2 = jt & 1;
            mmabf(c[i][jt], ah[i], bh[j][s2], bh[j][s2+2]);
            mmabf(c[i][jt], ah[i], bl[j][s2], bl[j][s2+2]);
            mmabf(c[i][jt], al[i], bh[j][s2], bh[j][s2+2]);
        }
    }
}

// store one thread's 32 staged B floats (rows = n, k range kh2*32..+32) into stage planes
__device__ __forceinline__ void storeB(char* st, int n, int kh2, const float* fB){
    char* Bh = st + 32768; char* Bl = st + 65536;
#pragma unroll
    for (int l = 0; l < 32; l += 4){
        uint32_t hp0, lp0, hp1, lp1;
        split2(fB[l],   fB[l+1], hp0, lp0);
        split2(fB[l+2], fB[l+3], hp1, lp1);
        uint32_t off = sw((uint32_t)n * 128 + (kh2 * 32 + l) * 2);
        *(uint2*)(Bh + off) = make_uint2(hp0, hp1);
        *(uint2*)(Bl + off) = make_uint2(lp0, lp1);
    }
}
// store one thread's 16 staged A floats (row m, k range q*16..+16)
__device__ __forceinline__ void storeA(char* st, int m, int q, const float* fA){
    char* Ah = st; char* Al = st + 16384;
#pragma unroll
    for (int j = 0; j < 16; j += 4){
        uint32_t hp0, lp0, hp1, lp1;
        split2(fA[j],   fA[j+1], hp0, lp0);
        split2(fA[j+2], fA[j+3], hp1, lp1);
        uint32_t off = sw((uint32_t)m * 128 + q * 32 + j * 2);
        *(uint2*)(Ah + off) = make_uint2(hp0, hp1);
        *(uint2*)(Al + off) = make_uint2(lp0, lp1);
    }
}

// ============ k1: h1 = gelu(x @ W1 + b1) -> bf16 hi/lo planes ============
// grid (2, 1000): nc = blockIdx.x (256-col chunk), g = blockIdx.y. 512 threads.
__global__ void __launch_bounds__(512, 1)
k1(const float* __restrict__ x, const float* __restrict__ W1, const float* __restrict__ b1)
{
    extern __shared__ char sm[];
    uint32_t sb = smem_u32(sm);
    const int nc = blockIdx.x, g = blockIdx.y;
    const int tid = threadIdx.x, lane = tid & 31, w = tid >> 5;
    const int wm = w & 1, wn = w >> 1;

    float* b1s = (float*)sm;
    if (tid < 256) b1s[tid] = b1[(size_t)g * 512 + nc * 256 + tid];

    const int mA = tid >> 2, qA = tid & 3;          // A staging map
    const int nB = tid & 255, khB = tid >> 8;       // B staging map
    const float* xA = x + mA * 128 + qA * 16;
    const float* wB = W1 + (size_t)g * 65536 + (size_t)khB * 32 * 512 + nc * 256 + nB;

    // ---- prologue: stage 0 ----
    {
        char* st = sm + 8192;
        float fA[16];
        const float4* xr = (const float4*)xA;
#pragma unroll
        for (int j = 0; j < 4; j++){ float4 v = xr[j]; fA[j*4]=v.x; fA[j*4+1]=v.y; fA[j*4+2]=v.z; fA[j*4+3]=v.w; }
        storeA(st, mA, qA, fA);
        float fB[32];
#pragma unroll
        for (int l = 0; l < 32; l++) fB[l] = wB[(size_t)l * 512];
        storeB(st, nB, khB, fB);
    }
    __syncthreads();

    float c[4][4][4];
#pragma unroll
    for (int i = 0; i < 4; i++)
#pragma unroll
    for (int jt = 0; jt < 4; jt++)
#pragma unroll
    for (int q = 0; q < 4; q++) c[i][jt][q] = 0.0f;
    Frag f = mk_frag(lane, wm, wn);

    // ---- kt = 0: stage stage-1 regs, MMA stage0, store stage1 ----
    {
        float fA[16], fB[32];
        const float4* xr = (const float4*)(xA + 64);
#pragma unroll
        for (int j = 0; j < 4; j++){ float4 v = xr[j]; fA[j*4]=v.x; fA[j*4+1]=v.y; fA[j*4+2]=v.z; fA[j*4+3]=v.w; }
#pragma unroll
        for (int l = 0; l < 32; l++) fB[l] = wB[(size_t)(64 + l) * 512];

        mma_ktile(sb + 8192, f, c);

        char* st = sm + 8192 + STAGE_BYTES;
        storeA(st, mA, qA, fA);
        storeB(st, nB, khB, fB);
    }
    __syncthreads();
    mma_ktile(sb + 8192 + STAGE_BYTES, f, c);

    // epilogue: bias + gelu + split-pack
#pragma unroll
    for (int i = 0; i < 4; i++)
#pragma unroll
    for (int jt = 0; jt < 4; jt++){
        int nl = wn * 32 + jt * 8 + 2 * (lane & 3);
        int r0 = wm * 64 + i * 16 + (lane >> 2);
        float bb0 = b1s[nl], bb1 = b1s[nl + 1];
        uint32_t hp, lp;
        float v0 = gelu(c[i][jt][0] + bb0);
        float v1 = gelu(c[i][jt][1] + bb1);
        split2(v0, v1, hp, lp);
        size_t idx = (size_t)g * 32768 + (size_t)r0 * 256 + (nc * 256 + nl) / 2;
        g_h1h[idx] = hp; g_h1l[idx] = lp;
        v0 = gelu(c[i][jt][2] + bb0);
        v1 = gelu(c[i][jt][3] + bb1);
        split2(v0, v1, hp, lp);
        idx += (size_t)8 * 256;
        g_h1h[idx] = hp; g_h1l[idx] = lp;
    }
}

// ============ k2: partial = sum_n gelu(h1 @ W2 + b2) * W3 ============
// grid (2, 1000). hdr: b2s@0 w3s@1024 red@2048(4KB). stages @8192.
__global__ void __launch_bounds__(512, 1)
k2(const float* __restrict__ W2, const float* __restrict__ b2, const float* __restrict__ W3)
{
    extern __shared__ char sm[];
    uint32_t sb = smem_u32(sm);
    const int nc = blockIdx.x, g = blockIdx.y;
    const int tid = threadIdx.x, lane = tid & 31, w = tid >> 5;
    const int wm = w & 1, wn = w >> 1;

    float* b2s = (float*)sm;
    float* w3s = (float*)(sm + 1024);
    if (tid < 256){
        b2s[tid] = b2[(size_t)g * 512 + nc * 256 + tid];
        w3s[tid] = W3[(size_t)g * 512 + nc * 256 + tid];
    }

    const char* hsrc = (const char*)g_h1h + (size_t)g * 131072;
    const char* lsrc = (const char*)g_h1l + (size_t)g * 131072;
    const int nB = tid & 255, khB = tid >> 8;
    const float* wB = W2 + (size_t)g * 262144 + (size_t)khB * 32 * 512 + nc * 256 + nB;

    float c[4][4][4];
#pragma unroll
    for (int i = 0; i < 4; i++)
#pragma unroll
    for (int jt = 0; jt < 4; jt++)
#pragma unroll
    for (int q = 0; q < 4; q++) c[i][jt][q] = 0.0f;
    Frag f = mk_frag(lane, wm, wn);

    // ---- prologue: stage 0 ----
    {
        uint32_t st = sb + 8192;
#pragma unroll
        for (int i2 = 0; i2 < 2; i2++){
            uint32_t ci = tid + i2 * 512, m = ci >> 3, kb = ci & 7;
            uint32_t d = sw(m * 128 + kb * 16);
            size_t so = (size_t)m * 1024 + kb * 16;
            CP16(st + d, hsrc + so);
            CP16(st + 16384 + d, lsrc + so);
        }
        CPCOMMIT();
        float fB[32];
#pragma unroll
        for (int l = 0; l < 32; l++) fB[l] = wB[(size_t)l * 512];
        storeB(sm + 8192, nB, khB, fB);
        CPWAIT0();
    }
    __syncthreads();

    for (int kt = 0; kt < 8; kt++){
        const int buf = kt & 1;
        const uint32_t cur = sb + 8192 + buf * STAGE_BYTES;
        const uint32_t nxt = sb + 8192 + (buf ^ 1) * STAGE_BYTES;
        float fB[32];
        if (kt < 7){
#pragma unroll
            for (int i2 = 0; i2 < 2; i2++){
                uint32_t ci = tid + i2 * 512, m = ci >> 3, kb = ci & 7;
                uint32_t d = sw(m * 128 + kb * 16);
                size_t so = (size_t)m * 1024 + (size_t)(kt + 1) * 128 + kb * 16;
                CP16(nxt + d, hsrc + so);
                CP16(nxt + 16384 + d, lsrc + so);
            }
            CPCOMMIT();
#pragma unroll
            for (int l = 0; l < 32; l++)
                fB[l] = wB[(size_t)((kt + 1) * 64 + l) * 512];
        }

        mma_ktile(cur, f, c);

        if (kt < 7){
            CPWAIT0();
            storeB(sm + 8192 + (buf ^ 1) * STAGE_BYTES, nB, khB, fB);
        }
        __syncthreads();
    }

    // epilogue: bias + gelu + W3-dot; shuffle + smem reduce over 8 N-warps
    float* red = (float*)(sm + 2048);
#pragma unroll
    for (int i = 0; i < 4; i++){
        float s0 = 0.0f, s1 = 0.0f;
#pragma unroll
        for (int jt = 0; jt < 4; jt++){
            int nl = wn * 32 + jt * 8 + 2 * (lane & 3);
            float bb0 = b2s[nl], bb1 = b2s[nl+1], ww0 = w3s[nl], ww1 = w3s[nl+1];
            s0 += gelu(c[i][jt][0] + bb0) * ww0 + gelu(c[i][jt][1] + bb1) * ww1;
            s1 += gelu(c[i][jt][2] + bb0) * ww0 + gelu(c[i][jt][3] + bb1) * ww1;
        }
        s0 += __shfl_xor_sync(0xFFFFFFFFu, s0, 1);
        s0 += __shfl_xor_sync(0xFFFFFFFFu, s0, 2);
        s1 += __shfl_xor_sync(0xFFFFFFFFu, s1, 1);
        s1 += __shfl_xor_sync(0xFFFFFFFFu, s1, 2);
        if ((lane & 3) == 0){
            int r0 = wm * 64 + i * 16 + (lane >> 2);
            red[r0 * 8 + wn] = s0;
            red[(r0 + 8) * 8 + wn] = s1;
        }
    }
    __syncthreads();
    if (tid < 128){
        const float* rr = red + tid * 8;
        float v = ((rr[0] + rr[1]) + (rr[2] + rr[3])) + ((rr[4] + rr[5]) + (rr[6] + rr[7]));
        g_part[((size_t)g * 2 + nc) * 128 + tid] = v;
    }
}

// ============ k3 ============
__global__ void k3(const float* __restrict__ b3, float* __restrict__ out)
{
    int idx = blockIdx.x * 256 + threadIdx.x;
    if (idx >= 128 * NG) return;
    int m = idx / NG;
    int g = idx - m * NG;
    const float* p = g_part + (size_t)g * 256 + m;
    out[idx] = b3[g] + p[0] + p[128];
}

extern "C" void kernel_launch(void* const* d_in, const int* in_sizes, int n_in,
                              void* d_out, int out_size)
{
    const float* x  = (const float*)d_in[0];
    const float* W1 = (const float*)d_in[1];
    const float* b1 = (const float*)d_in[2];
    const float* W2 = (const float*)d_in[3];
    const float* b2 = (const float*)d_in[4];
    const float* W3 = (const float*)d_in[5];
    const float* b3 = (const float*)d_in[6];
    float* out = (float*)d_out;

    cudaFuncSetAttribute(k1, cudaFuncAttributeMaxDynamicSharedMemorySize, SM_BYTES);
    cudaFuncSetAttribute(k2, cudaFuncAttributeMaxDynamicSharedMemorySize, SM_BYTES);

    dim3 grid(2, NG);
    k1<<<grid, 512, SM_BYTES>>>(x, W1, b1);
    k2<<<grid, 512, SM_BYTES>>>(W2, b2, W3);
    k3<<<(128 * NG + 255) / 256, 256>>>(b3, out);
}

// round 7
// speedup vs baseline: 1.0082x; 1.0082x over previous
#include <cuda_runtime.h>
#include <math.h>
#include <stdint.h>

#define NG 1000

__device__ __align__(16) uint32_t g_h1h[(size_t)NG * 128 * 256];  // [g][m][n/2] bf16-hi pairs
__device__ __align__(16) uint32_t g_h1l[(size_t)NG * 128 * 256];  // bf16-lo pairs
__device__ float g_part[(size_t)NG * 2 * 128];

#define STAGE_BYTES 98304          // Ah 16K | Al 16K | Bh 32K | Bl 32K
#define SM_BYTES (8192 + 2 * STAGE_BYTES)   // 204800

__device__ __forceinline__ uint32_t smem_u32(const void* p){
    uint32_t a;
    asm("{ .reg .u64 t; cvta.to.shared.u64 t, %1; cvt.u32.u64 %0, t; }" : "=r"(a) : "l"(p));
    return a;
}
__device__ __forceinline__ uint32_t sw(uint32_t x){ return x ^ ((x >> 3) & 0x70u); }

__device__ __forceinline__ void split2(float f0, float f1, uint32_t& hp, uint32_t& lp){
    asm("cvt.rn.bf16x2.f32 %0, %1, %2;" : "=r"(hp) : "f"(f1), "f"(f0));
    float h1f = __uint_as_float(hp & 0xFFFF0000u);
    float h0f = __uint_as_float(hp << 16);
    asm("cvt.rn.bf16x2.f32 %0, %1, %2;" : "=r"(lp) : "f"(f1 - h1f), "f"(f0 - h0f));
}
__device__ __forceinline__ float gelu(float v){
    return 0.5f * v * (1.0f + erff(v * 0.70710678118654752440f));
}
__device__ __forceinline__ void ldsm4(uint32_t* r, uint32_t a){
    asm volatile("ldmatrix.sync.aligned.m8n8.x4.shared.b16 {%0,%1,%2,%3}, [%4];"
      : "=r"(r[0]), "=r"(r[1]), "=r"(r[2]), "=r"(r[3]) : "r"(a));
}
__device__ __forceinline__ void mmabf(float* c, const uint32_t* a, uint32_t b0, uint32_t b1){
    asm volatile("mma.sync.aligned.m16n8k16.row.col.f32.bf16.bf16.f32 "
      "{%0,%1,%2,%3},{%4,%5,%6,%7},{%8,%9},{%0,%1,%2,%3};"
      : "+f"(c[0]), "+f"(c[1]), "+f"(c[2]), "+f"(c[3])
      : "r"(a[0]), "r"(a[1]), "r"(a[2]), "r"(a[3]), "r"(b0), "r"(b1));
}
#define CP16(d,s)  asm volatile("cp.async.cg.shared.global [%0], [%1], 16;" :: "r"(d), "l"(s) : "memory")
#define CPCOMMIT() asm volatile("cp.async.commit_group;" ::: "memory")
#define CPWAIT0()  asm volatile("cp.async.wait_group 0;" ::: "memory")

struct Frag { uint32_t offA, mA, offB, mB, ksel; };

__device__ __forceinline__ Frag mk_frag(int lane, int wm, int wn){
    Frag f;
    uint32_t rA = wm * 64 + (lane & 7) + ((lane >> 3) & 1) * 8;
    uint32_t rB = wn * 32 + (lane & 7) + ((lane >> 3) & 1) * 8;
    f.ksel = ((lane >> 4) & 1) * 16;
    f.mA = (rA & 7) << 4;  f.mB = (rB & 7) << 4;
    f.offA = rA * 128;     f.offB = rB * 128;
    return f;
}

// one K=64 tile. A planes [128m][64k] (hi@st, lo@st+16K); B planes [256n][64k] (hi@st+32K, lo@st+64K)
__device__ __forceinline__ void mma_ktile(uint32_t st, const Frag& f, float c[4][4][4])
{
    uint32_t Ah = st, Al = st + 16384, Bh = st + 32768, Bl = st + 65536;
#pragma unroll
    for (int ks = 0; ks < 4; ks++){
        uint32_t ka = ks * 32 + f.ksel;
        uint32_t ao = f.offA + (ka ^ f.mA);
        uint32_t bo = f.offB + (ka ^ f.mB);
        uint32_t ah[4][4], al[4][4], bh[2][4], bl[2][4];
#pragma unroll
        for (int i = 0; i < 4; i++){ ldsm4(ah[i], Ah + ao + i*2048u); ldsm4(al[i], Al + ao + i*2048u); }
#pragma unroll
        for (int j = 0; j < 2; j++){ ldsm4(bh[j], Bh + bo + j*2048u); ldsm4(bl[j], Bl + bo + j*2048u); }
#pragma unroll
        for (int i = 0; i < 4; i++)
#pragma unroll
        for (int jt = 0; jt < 4; jt++){
            int j = jt >> 1, s2 = jt & 1;
            mmabf(c[i][jt], ah[i], bh[j][s2], bh[j][s2+2]);
            mmabf(c[i][jt], ah[i], bl[j][s2], bl[j][s2+2]);
            mmabf(c[i][jt], al[i], bh[j][s2], bh[j][s2+2]);
        }
    }
}

// store one thread's 16 B floats (row n, k range kh2*32 + half*16 .. +16)
__device__ __forceinline__ void storeB16(char* st, int n, int kh2, int half, const float* fB){
    char* Bh = st + 32768; char* Bl = st + 65536;
#pragma unroll
    for (int l = 0; l < 16; l += 4){
        uint32_t hp0, lp0, hp1, lp1;
        split2(fB[l],   fB[l+1], hp0, lp0);
        split2(fB[l+2], fB[l+3], hp1, lp1);
        uint32_t off = sw((uint32_t)n * 128 + (kh2 * 32 + half * 16 + l) * 2);
        *(uint2*)(Bh + off) = make_uint2(hp0, hp1);
        *(uint2*)(Bl + off) = make_uint2(lp0, lp1);
    }
}
// store one thread's 16 A floats (row m, k range q*16..+16)
__device__ __forceinline__ void storeA(char* st, int m, int q, const float* fA){
    char* Ah = st; char* Al = st + 16384;
#pragma unroll
    for (int j = 0; j < 16; j += 4){
        uint32_t hp0, lp0, hp1, lp1;
        split2(fA[j],   fA[j+1], hp0, lp0);
        split2(fA[j+2], fA[j+3], hp1, lp1);
        uint32_t off = sw((uint32_t)m * 128 + q * 32 + j * 2);
        *(uint2*)(Ah + off) = make_uint2(hp0, hp1);
        *(uint2*)(Al + off) = make_uint2(lp0, lp1);
    }
}

// ============ k1: h1 = gelu(x @ W1 + b1) -> bf16 hi/lo planes ============
// grid (2, 1000): nc = blockIdx.x (256-col chunk), g = blockIdx.y. 512 threads.
__global__ void __launch_bounds__(512, 1)
k1(const float* __restrict__ x, const float* __restrict__ W1, const float* __restrict__ b1)
{
    extern __shared__ char sm[];
    uint32_t sb = smem_u32(sm);
    const int nc = blockIdx.x, g = blockIdx.y;
    const int tid = threadIdx.x, lane = tid & 31, w = tid >> 5;
    const int wm = w & 1, wn = w >> 1;

    float* b1s = (float*)sm;
    if (tid < 256) b1s[tid] = b1[(size_t)g * 512 + nc * 256 + tid];

    const int mA = tid >> 2, qA = tid & 3;
    const int nB = tid & 255, khB = tid >> 8;
    const float* xA = x + mA * 128 + qA * 16;
    const float* wB = W1 + (size_t)g * 65536 + (size_t)khB * 32 * 512 + nc * 256 + nB;

    // ---- prologue: A for BOTH stages + B stage0 (all transient regs) ----
#pragma unroll
    for (int s = 0; s < 2; s++){
        float fA[16];
        const float4* xr = (const float4*)(xA + s * 64);
#pragma unroll
        for (int j = 0; j < 4; j++){ float4 v = xr[j]; fA[j*4]=v.x; fA[j*4+1]=v.y; fA[j*4+2]=v.z; fA[j*4+3]=v.w; }
        storeA(sm + 8192 + s * STAGE_BYTES, mA, qA, fA);
    }
#pragma unroll
    for (int h = 0; h < 2; h++){
        float fB[16];
#pragma unroll
        for (int l = 0; l < 16; l++) fB[l] = wB[(size_t)(h * 16 + l) * 512];
        storeB16(sm + 8192, nB, khB, h, fB);
    }
    __syncthreads();

    float c[4][4][4];
#pragma unroll
    for (int i = 0; i < 4; i++)
#pragma unroll
    for (int jt = 0; jt < 4; jt++)
#pragma unroll
    for (int q = 0; q < 4; q++) c[i][jt][q] = 0.0f;
    Frag f = mk_frag(lane, wm, wn);

    mma_ktile(sb + 8192, f, c);

    // load + store B stage1 (transient, after stage0 MMA)
#pragma unroll
    for (int h = 0; h < 2; h++){
        float fB[16];
#pragma unroll
        for (int l = 0; l < 16; l++) fB[l] = wB[(size_t)(64 + h * 16 + l) * 512];
        storeB16(sm + 8192 + STAGE_BYTES, nB, khB, h, fB);
    }
    __syncthreads();
    mma_ktile(sb + 8192 + STAGE_BYTES, f, c);

    // epilogue: bias + gelu + split-pack
#pragma unroll
    for (int i = 0; i < 4; i++)
#pragma unroll
    for (int jt = 0; jt < 4; jt++){
        int nl = wn * 32 + jt * 8 + 2 * (lane & 3);
        int r0 = wm * 64 + i * 16 + (lane >> 2);
        float bb0 = b1s[nl], bb1 = b1s[nl + 1];
        uint32_t hp, lp;
        float v0 = gelu(c[i][jt][0] + bb0);
        float v1 = gelu(c[i][jt][1] + bb1);
        split2(v0, v1, hp, lp);
        size_t idx = (size_t)g * 32768 + (size_t)r0 * 256 + (nc * 256 + nl) / 2;
        g_h1h[idx] = hp; g_h1l[idx] = lp;
        v0 = gelu(c[i][jt][2] + bb0);
        v1 = gelu(c[i][jt][3] + bb1);
        split2(v0, v1, hp, lp);
        idx += (size_t)8 * 256;
        g_h1h[idx] = hp; g_h1l[idx] = lp;
    }
}

// ============ k2: partial = sum_n gelu(h1 @ W2 + b2) * W3 ============
// grid (2, 1000). hdr: b2s@0 w3s@1024 red@2048(4KB). stages @8192.
__global__ void __launch_bounds__(512, 1)
k2(const float* __restrict__ W2, const float* __restrict__ b2, const float* __restrict__ W3)
{
    extern __shared__ char sm[];
    uint32_t sb = smem_u32(sm);
    const int nc = blockIdx.x, g = blockIdx.y;
    const int tid = threadIdx.x, lane = tid & 31, w = tid >> 5;
    const int wm = w & 1, wn = w >> 1;

    float* b2s = (float*)sm;
    float* w3s = (float*)(sm + 1024);
    if (tid < 256){
        b2s[tid] = b2[(size_t)g * 512 + nc * 256 + tid];
        w3s[tid] = W3[(size_t)g * 512 + nc * 256 + tid];
    }

    const char* hsrc = (const char*)g_h1h + (size_t)g * 131072;
    const char* lsrc = (const char*)g_h1l + (size_t)g * 131072;
    const int nB = tid & 255, khB = tid >> 8;
    const float* wB = W2 + (size_t)g * 262144 + (size_t)khB * 32 * 512 + nc * 256 + nB;

    float c[4][4][4];
#pragma unroll
    for (int i = 0; i < 4; i++)
#pragma unroll
    for (int jt = 0; jt < 4; jt++)
#pragma unroll
    for (int q = 0; q < 4; q++) c[i][jt][q] = 0.0f;
    Frag f = mk_frag(lane, wm, wn);

    // ---- prologue: stage 0 ----
    {
        uint32_t st = sb + 8192;
#pragma unroll
        for (int i2 = 0; i2 < 2; i2++){
            uint32_t ci = tid + i2 * 512, m = ci >> 3, kb = ci & 7;
            uint32_t d = sw(m * 128 + kb * 16);
            size_t so = (size_t)m * 1024 + kb * 16;
            CP16(st + d, hsrc + so);
            CP16(st + 16384 + d, lsrc + so);
        }
        CPCOMMIT();
#pragma unroll
        for (int h = 0; h < 2; h++){
            float fB[16];
#pragma unroll
            for (int l = 0; l < 16; l++) fB[l] = wB[(size_t)(h * 16 + l) * 512];
            storeB16(sm + 8192, nB, khB, h, fB);
        }
        CPWAIT0();
    }
    __syncthreads();

    for (int kt = 0; kt < 8; kt++){
        const int buf = kt & 1;
        const uint32_t cur = sb + 8192 + buf * STAGE_BYTES;
        const uint32_t nxt = sb + 8192 + (buf ^ 1) * STAGE_BYTES;
        char* nxtp = sm + 8192 + (buf ^ 1) * STAGE_BYTES;
        float fPre[16];
        if (kt < 7){
#pragma unroll
            for (int i2 = 0; i2 < 2; i2++){
                uint32_t ci = tid + i2 * 512, m = ci >> 3, kb = ci & 7;
                uint32_t d = sw(m * 128 + kb * 16);
                size_t so = (size_t)m * 1024 + (size_t)(kt + 1) * 128 + kb * 16;
                CP16(nxt + d, hsrc + so);
                CP16(nxt + 16384 + d, lsrc + so);
            }
            CPCOMMIT();
            // hold only 16 floats across the MMA
#pragma unroll
            for (int l = 0; l < 16; l++)
                fPre[l] = wB[(size_t)((kt + 1) * 64 + l) * 512];
        }

        mma_ktile(cur, f, c);

        if (kt < 7){
            storeB16(nxtp, nB, khB, 0, fPre);
            float fPost[16];
#pragma unroll
            for (int l = 0; l < 16; l++)
                fPost[l] = wB[(size_t)((kt + 1) * 64 + 16 + l) * 512];
            storeB16(nxtp, nB, khB, 1, fPost);
            CPWAIT0();
        }
        __syncthreads();
    }

    // epilogue: bias + gelu + W3-dot; shuffle + smem reduce over 8 N-warps
    float* red = (float*)(sm + 2048);
#pragma unroll
    for (int i = 0; i < 4; i++){
        float s0 = 0.0f, s1 = 0.0f;
#pragma unroll
        for (int jt = 0; jt < 4; jt++){
            int nl = wn * 32 + jt * 8 + 2 * (lane & 3);
            float bb0 = b2s[nl], bb1 = b2s[nl+1], ww0 = w3s[nl], ww1 = w3s[nl+1];
            s0 += gelu(c[i][jt][0] + bb0) * ww0 + gelu(c[i][jt][1] + bb1) * ww1;
            s1 += gelu(c[i][jt][2] + bb0) * ww0 + gelu(c[i][jt][3] + bb1) * ww1;
        }
        s0 += __shfl_xor_sync(0xFFFFFFFFu, s0, 1);
        s0 += __shfl_xor_sync(0xFFFFFFFFu, s0, 2);
        s1 += __shfl_xor_sync(0xFFFFFFFFu, s1, 1);
        s1 += __shfl_xor_sync(0xFFFFFFFFu, s1, 2);
        if ((lane & 3) == 0){
            int r0 = wm * 64 + i * 16 + (lane >> 2);
            red[r0 * 8 + wn] = s0;
            red[(r0 + 8) * 8 + wn] = s1;
        }
    }
    __syncthreads();
    if (tid < 128){
        const float* rr = red + tid * 8;
        float v = ((rr[0] + rr[1]) + (rr[2] + rr[3])) + ((rr[4] + rr[5]) + (rr[6] + rr[7]));
        g_part[((size_t)g * 2 + nc) * 128 + tid] = v;
    }
}

// ============ k3 ============
__global__ void k3(const float* __restrict__ b3, float* __restrict__ out)
{
    int idx = blockIdx.x * 256 + threadIdx.x;
    if (idx >= 128 * NG) return;
    int m = idx / NG;
    int g = idx - m * NG;
    const float* p = g_part + (size_t)g * 256 + m;
    out[idx] = b3[g] + p[0] + p[128];
}

extern "C" void kernel_launch(void* const* d_in, const int* in_sizes, int n_in,
                              void* d_out, int out_size)
{
    const float* x  = (const float*)d_in[0];
    const float* W1 = (const float*)d_in[1];
    const float* b1 = (const float*)d_in[2];
    const float* W2 = (const float*)d_in[3];
    const float* b2 = (const float*)d_in[4];
    const float* W3 = (const float*)d_in[5];
    const float* b3 = (const float*)d_in[6];
    float* out = (float*)d_out;

    cudaFuncSetAttribute(k1, cudaFuncAttributeMaxDynamicSharedMemorySize, SM_BYTES);
    cudaFuncSetAttribute(k2, cudaFuncAttributeMaxDynamicSharedMemorySize, SM_BYTES);

    dim3 grid(2, NG);
    k1<<<grid, 512, SM_BYTES>>>(x, W1, b1);
    k2<<<grid, 512, SM_BYTES>>>(W2, b2, W3);
    k3<<<(128 * NG + 255) / 256, 256>>>(b3, out);
}

// round 8
// speedup vs baseline: 1.2158x; 1.2060x over previous
#include <cuda_runtime.h>
#include <math.h>
#include <stdint.h>

#define NG 1000

__device__ __align__(16) uint32_t g_h1h[(size_t)NG * 128 * 256];  // [g][m][n/2] bf16-hi pairs
__device__ __align__(16) uint32_t g_h1l[(size_t)NG * 128 * 256];  // bf16-lo pairs
__device__ float g_part[(size_t)NG * 4 * 128];

// k1 smem: b1s@0(1KB) | A slots@1024: 4 x 16KB (Ah 8K, Al 8K) | B ring@66560: 2 x 16KB
#define K1_ABASE 1024
#define K1_BBASE 66560
#define SM1_BYTES 99328
// k2 smem: b2s@0 w3s@512 red@1024(2KB) | ring@4096: 3 x 32KB (Ah,Al,Bh,Bl 8K each)
#define K2_RING 4096
#define SM2_BYTES 102400

__device__ __forceinline__ uint32_t smem_u32(const void* p){
    uint32_t a;
    asm("{ .reg .u64 t; cvta.to.shared.u64 t, %1; cvt.u32.u64 %0, t; }" : "=r"(a) : "l"(p));
    return a;
}
// 64-byte-row swizzle (Swizzle<2,4,3>): XOR bits[4:5] with bits[7:8]
__device__ __forceinline__ uint32_t sw64(uint32_t x){ return x ^ ((x >> 3) & 0x30u); }

__device__ __forceinline__ void split2(float f0, float f1, uint32_t& hp, uint32_t& lp){
    asm("cvt.rn.bf16x2.f32 %0, %1, %2;" : "=r"(hp) : "f"(f1), "f"(f0));
    float h1f = __uint_as_float(hp & 0xFFFF0000u);
    float h0f = __uint_as_float(hp << 16);
    asm("cvt.rn.bf16x2.f32 %0, %1, %2;" : "=r"(lp) : "f"(f1 - h1f), "f"(f0 - h0f));
}
__device__ __forceinline__ float gelu(float v){
    return 0.5f * v * (1.0f + erff(v * 0.70710678118654752440f));
}
__device__ __forceinline__ void ldsm4(uint32_t* r, uint32_t a){
    asm volatile("ldmatrix.sync.aligned.m8n8.x4.shared.b16 {%0,%1,%2,%3}, [%4];"
      : "=r"(r[0]), "=r"(r[1]), "=r"(r[2]), "=r"(r[3]) : "r"(a));
}
__device__ __forceinline__ void mmabf(float* c, const uint32_t* a, uint32_t b0, uint32_t b1){
    asm volatile("mma.sync.aligned.m16n8k16.row.col.f32.bf16.bf16.f32 "
      "{%0,%1,%2,%3},{%4,%5,%6,%7},{%8,%9},{%0,%1,%2,%3};"
      : "+f"(c[0]), "+f"(c[1]), "+f"(c[2]), "+f"(c[3])
      : "r"(a[0]), "r"(a[1]), "r"(a[2]), "r"(a[3]), "r"(b0), "r"(b1));
}
#define CP16(d,s)  asm volatile("cp.async.cg.shared.global [%0], [%1], 16;" :: "r"(d), "l"(s) : "memory")
#define CPCOMMIT() asm volatile("cp.async.commit_group;" ::: "memory")
#define CPWAIT1()  asm volatile("cp.async.wait_group 1;" ::: "memory")

struct Frag { uint32_t offA, mA, offB, mB, ksel; };

__device__ __forceinline__ Frag mk_frag(int lane, int wm, int wn){
    Frag f;
    uint32_t rA = wm * 64 + (lane & 7) + ((lane >> 3) & 1) * 8;
    uint32_t rB = wn * 32 + (lane & 7) + ((lane >> 3) & 1) * 8;
    f.ksel = ((lane >> 4) & 1) * 16;
    f.mA = ((rA >> 1) & 3) << 4;  f.mB = ((rB >> 1) & 3) << 4;
    f.offA = rA * 64;             f.offB = rB * 64;
    return f;
}

// one K=32 tile, 64B rows. A planes: aB (hi), aB+8192 (lo), 128 rows.
// B planes: bB (hi), bB+8192 (lo), 128 rows. c covers 64Mx32N per warp.
__device__ __forceinline__ void mma32(uint32_t aB, uint32_t bB, const Frag& f, float c[4][4][4])
{
#pragma unroll
    for (int ks = 0; ks < 2; ks++){
        uint32_t ka = ks * 32 + f.ksel;
        uint32_t ao = f.offA + (ka ^ f.mA);
        uint32_t bo = f.offB + (ka ^ f.mB);
        uint32_t ah[4][4], al[4][4], bh[2][4], bl[2][4];
#pragma unroll
        for (int i = 0; i < 4; i++){ ldsm4(ah[i], aB + ao + i*1024u); ldsm4(al[i], aB + 8192u + ao + i*1024u); }
#pragma unroll
        for (int j = 0; j < 2; j++){ ldsm4(bh[j], bB + bo + j*1024u); ldsm4(bl[j], bB + 8192u + bo + j*1024u); }
#pragma unroll
        for (int i = 0; i < 4; i++)
#pragma unroll
        for (int jt = 0; jt < 4; jt++){
            int j = jt >> 1, s2 = jt & 1;
            mmabf(c[i][jt], ah[i], bh[j][s2], bh[j][s2+2]);
            mmabf(c[i][jt], ah[i], bl[j][s2], bl[j][s2+2]);
            mmabf(c[i][jt], al[i], bh[j][s2], bh[j][s2+2]);
        }
    }
}

// store one thread's 16 B floats (row n, k sub-half kh of K32 stage) into B slot planes
__device__ __forceinline__ void storeB(char* bB, int n, int kh, const float* fB){
    char* Bh = bB; char* Bl = bB + 8192;
#pragma unroll
    for (int l = 0; l < 16; l += 4){
        uint32_t hp0, lp0, hp1, lp1;
        split2(fB[l],   fB[l+1], hp0, lp0);
        split2(fB[l+2], fB[l+3], hp1, lp1);
        uint32_t off = sw64((uint32_t)n * 64 + kh * 32 + l * 2);
        *(uint2*)(Bh + off) = make_uint2(hp0, hp1);
        *(uint2*)(Bl + off) = make_uint2(lp0, lp1);
    }
}

// ============ k1: h1 = gelu(x @ W1 + b1) -> bf16 hi/lo planes ============
// grid (4, 1000): nc = 128-col chunk, g = gene. 256 threads, 2 CTAs/SM.
__global__ void __launch_bounds__(256, 2)
k1(const float* __restrict__ x, const float* __restrict__ W1, const float* __restrict__ b1)
{
    extern __shared__ char sm[];
    uint32_t sb = smem_u32(sm);
    const int nc = blockIdx.x, g = blockIdx.y;
    const int tid = threadIdx.x, lane = tid & 31, w = tid >> 5;
    const int wm = w & 1, wn = w >> 1;

    float* b1s = (float*)sm;
    if (tid < 128) b1s[tid] = b1[(size_t)g * 512 + nc * 128 + tid];

    // ---- prestage A = x into 4 K32 slots (hi/lo) ----
    {
        int m = tid >> 1, h = tid & 1;
        const float4* xr = (const float4*)(x + m * 128 + h * 64);
#pragma unroll
        for (int j4 = 0; j4 < 16; j4++){
            float4 v = xr[j4];
            int l = j4 * 4;
            int slot = h * 2 + (l >> 5);
            int kk = l & 31;
            uint32_t hp0, lp0, hp1, lp1;
            split2(v.x, v.y, hp0, lp0);
            split2(v.z, v.w, hp1, lp1);
            uint32_t off = sw64((uint32_t)m * 64 + kk * 2);
            char* Ah = sm + K1_ABASE + slot * 16384;
            *(uint2*)(Ah + off) = make_uint2(hp0, hp1);
            *(uint2*)(Ah + 8192 + off) = make_uint2(lp0, lp1);
        }
    }
    // ---- B stage 0 ----
    const int nB = tid & 127, khB = tid >> 7;
    const float* wB = W1 + (size_t)g * 65536 + (size_t)khB * 16 * 512 + nc * 128 + nB;
    {
        float fB[16];
#pragma unroll
        for (int l = 0; l < 16; l++) fB[l] = wB[(size_t)l * 512];
        storeB(sm + K1_BBASE, nB, khB, fB);
    }
    __syncthreads();

    float c[4][4][4];
#pragma unroll
    for (int i = 0; i < 4; i++)
#pragma unroll
    for (int jt = 0; jt < 4; jt++)
#pragma unroll
    for (int q = 0; q < 4; q++) c[i][jt][q] = 0.0f;
    Frag f = mk_frag(lane, wm, wn);

#pragma unroll
    for (int kt = 0; kt < 4; kt++){
        float fB[16];
        if (kt < 3){
#pragma unroll
            for (int l = 0; l < 16; l++)
                fB[l] = wB[(size_t)((kt + 1) * 32 + l) * 512];
        }
        mma32(sb + K1_ABASE + kt * 16384, sb + K1_BBASE + (kt & 1) * 16384, f, c);
        if (kt < 3)
            storeB(sm + K1_BBASE + ((kt + 1) & 1) * 16384, nB, khB, fB);
        __syncthreads();
    }

    // epilogue: bias + gelu + split-pack
#pragma unroll
    for (int i = 0; i < 4; i++)
#pragma unroll
    for (int jt = 0; jt < 4; jt++){
        int nl = wn * 32 + jt * 8 + 2 * (lane & 3);
        int r0 = wm * 64 + i * 16 + (lane >> 2);
        float bb0 = b1s[nl], bb1 = b1s[nl + 1];
        uint32_t hp, lp;
        float v0 = gelu(c[i][jt][0] + bb0);
        float v1 = gelu(c[i][jt][1] + bb1);
        split2(v0, v1, hp, lp);
        size_t idx = (size_t)g * 32768 + (size_t)r0 * 256 + nc * 64 + nl / 2;
        g_h1h[idx] = hp; g_h1l[idx] = lp;
        v0 = gelu(c[i][jt][2] + bb0);
        v1 = gelu(c[i][jt][3] + bb1);
        split2(v0, v1, hp, lp);
        idx += (size_t)8 * 256;
        g_h1h[idx] = hp; g_h1l[idx] = lp;
    }
}

// ============ k2: partial = sum_n gelu(h1 @ W2 + b2) * W3 ============
// grid (4, 1000). 256 threads, 2 CTAs/SM. 16 K32 stages, 3-slot ring.
__global__ void __launch_bounds__(256, 2)
k2(const float* __restrict__ W2, const float* __restrict__ b2, const float* __restrict__ W3)
{
    extern __shared__ char sm[];
    uint32_t sb = smem_u32(sm);
    const int nc = blockIdx.x, g = blockIdx.y;
    const int tid = threadIdx.x, lane = tid & 31, w = tid >> 5;
    const int wm = w & 1, wn = w >> 1;

    float* b2s = (float*)sm;
    float* w3s = (float*)(sm + 512);
    if (tid < 128){
        b2s[tid] = b2[(size_t)g * 512 + nc * 128 + tid];
        w3s[tid] = W3[(size_t)g * 512 + nc * 128 + tid];
    }

    const char* hsrc = (const char*)g_h1h + (size_t)g * 131072;
    const char* lsrc = (const char*)g_h1l + (size_t)g * 131072;
    const int nB = tid & 127, khB = tid >> 7;
    const float* wB = W2 + (size_t)g * 262144 + (size_t)khB * 16 * 512 + nc * 128 + nB;
    const uint32_t ciM = tid >> 2, ciG = tid & 3;  // cp.async granule map (1/thread/plane... x1 since 128*4/256=2? see below)

    float c[4][4][4];
#pragma unroll
    for (int i = 0; i < 4; i++)
#pragma unroll
    for (int jt = 0; jt < 4; jt++)
#pragma unroll
    for (int q = 0; q < 4; q++) c[i][jt][q] = 0.0f;
    Frag f = mk_frag(lane, wm, wn);

    // cp.async helper: stage kt's A planes into ring slot s (512 granules/plane, 2/thread/plane)
    auto cpA = [&](int kt, int s){
        uint32_t slot = sb + K2_RING + s * 32768;
#pragma unroll
        for (int i2 = 0; i2 < 2; i2++){
            uint32_t ci = tid + i2 * 256;
            uint32_t m = ci >> 2, g4 = ci & 3;
            uint32_t d = m * 64 + 16u * (g4 ^ ((m >> 1) & 3));
            size_t so = (size_t)m * 1024 + (size_t)kt * 64 + g4 * 16;
            CP16(slot + d, hsrc + so);
            CP16(slot + 8192 + d, lsrc + so);
        }
    };

    // ---- prologue: A(0), A(1) async; B(0), B(1) sync ----
    cpA(0, 0); CPCOMMIT();
    cpA(1, 1); CPCOMMIT();
#pragma unroll
    for (int s = 0; s < 2; s++){
        float fB[16];
#pragma unroll
        for (int l = 0; l < 16; l++) fB[l] = wB[(size_t)(s * 32 + l) * 512];
        storeB(sm + K2_RING + s * 32768 + 16384, nB, khB, fB);
    }

    for (int kt = 0; kt < 16; kt++){
        CPWAIT1();
        __syncthreads();
        const int s2 = (kt + 2) % 3;
        if (kt < 14) cpA(kt + 2, s2);
        CPCOMMIT();
        float fB[16];
        if (kt < 14){
#pragma unroll
            for (int l = 0; l < 16; l++)
                fB[l] = wB[(size_t)((kt + 2) * 32 + l) * 512];
        }

        uint32_t cur = sb + K2_RING + (kt % 3) * 32768;
        mma32(cur, cur + 16384, f, c);

        if (kt < 14)
            storeB(sm + K2_RING + s2 * 32768 + 16384, nB, khB, fB);
    }
    __syncthreads();

    // epilogue: bias + gelu + W3-dot; quad shuffle + cross-warp smem reduce
    float* red = (float*)(sm + 1024);
#pragma unroll
    for (int i = 0; i < 4; i++){
        float s0 = 0.0f, s1 = 0.0f;
#pragma unroll
        for (int jt = 0; jt < 4; jt++){
            int nl = wn * 32 + jt * 8 + 2 * (lane & 3);
            float bb0 = b2s[nl], bb1 = b2s[nl+1], ww0 = w3s[nl], ww1 = w3s[nl+1];
            s0 += gelu(c[i][jt][0] + bb0) * ww0 + gelu(c[i][jt][1] + bb1) * ww1;
            s1 += gelu(c[i][jt][2] + bb0) * ww0 + gelu(c[i][jt][3] + bb1) * ww1;
        }
        s0 += __shfl_xor_sync(0xFFFFFFFFu, s0, 1);
        s0 += __shfl_xor_sync(0xFFFFFFFFu, s0, 2);
        s1 += __shfl_xor_sync(0xFFFFFFFFu, s1, 1);
        s1 += __shfl_xor_sync(0xFFFFFFFFu, s1, 2);
        if ((lane & 3) == 0){
            int r0 = wm * 64 + i * 16 + (lane >> 2);
            red[r0 * 4 + wn] = s0;
            red[(r0 + 8) * 4 + wn] = s1;
        }
    }
    __syncthreads();
    if (tid < 128){
        const float* rr = red + tid * 4;
        g_part[((size_t)g * 4 + nc) * 128 + tid] = (rr[0] + rr[1]) + (rr[2] + rr[3]);
    }
}

// ============ k3 ============
__global__ void k3(const float* __restrict__ b3, float* __restrict__ out)
{
    int idx = blockIdx.x * 256 + threadIdx.x;
    if (idx >= 128 * NG) return;
    int m = idx / NG;
    int g = idx - m * NG;
    const float* p = g_part + (size_t)g * 512 + m;
    out[idx] = b3[g] + ((p[0] + p[128]) + (p[256] + p[384]));
}

extern "C" void kernel_launch(void* const* d_in, const int* in_sizes, int n_in,
                              void* d_out, int out_size)
{
    const float* x  = (const float*)d_in[0];
    const float* W1 = (const float*)d_in[1];
    const float* b1 = (const float*)d_in[2];
    const float* W2 = (const float*)d_in[3];
    const float* b2 = (const float*)d_in[4];
    const float* W3 = (const float*)d_in[5];
    const float* b3 = (const float*)d_in[6];
    float* out = (float*)d_out;

    cudaFuncSetAttribute(k1, cudaFuncAttributeMaxDynamicSharedMemorySize, SM1_BYTES);
    cudaFuncSetAttribute(k2, cudaFuncAttributeMaxDynamicSharedMemorySize, SM2_BYTES);

    dim3 grid(4, NG);
    k1<<<grid, 256, SM1_BYTES>>>(x, W1, b1);
    k2<<<grid, 256, SM2_BYTES>>>(W2, b2, W3);
    k3<<<(128 * NG + 255) / 256, 256>>>(b3, out);
}

// round 9
// speedup vs baseline: 1.3255x; 1.0902x over previous
#include <cuda_runtime.h>
#include <math.h>
#include <stdint.h>

#define NG 1000

// x as pre-swizzled bf16 hi/lo slot image: 4 slots x (hi 8K | lo 8K)
__device__ __align__(16) char g_ximg[65536];
// h1 as pre-swizzled slot image per gene: 16 slots x 16KB = 256KB/gene
__device__ __align__(16) char g_h1img[(size_t)NG * 262144];
__device__ float g_part[(size_t)NG * 4 * 128];

// k1 smem: b1s@0 | Wf32@1024(16K) | Bbf16@17408(16K) | A@33792(64K)
#define K1_WF   1024
#define K1_B    17408
#define K1_A    33792
#define SM1_BYTES 99328
// k2 smem: b2s@0 w3s@512 | Aring@1024(3x16K) | Bbf16@50176(2x16K) | Wf32@82944(2x16K)
#define K2_A    1024
#define K2_B    50176
#define K2_WF   82944
#define SM2_BYTES 115712

__device__ __forceinline__ uint32_t smem_u32(const void* p){
    uint32_t a;
    asm("{ .reg .u64 t; cvta.to.shared.u64 t, %1; cvt.u32.u64 %0, t; }" : "=r"(a) : "l"(p));
    return a;
}
__device__ __forceinline__ uint32_t sw64(uint32_t x){ return x ^ ((x >> 3) & 0x30u); }

__device__ __forceinline__ void split2(float f0, float f1, uint32_t& hp, uint32_t& lp){
    asm("cvt.rn.bf16x2.f32 %0, %1, %2;" : "=r"(hp) : "f"(f1), "f"(f0));
    float h1f = __uint_as_float(hp & 0xFFFF0000u);
    float h0f = __uint_as_float(hp << 16);
    asm("cvt.rn.bf16x2.f32 %0, %1, %2;" : "=r"(lp) : "f"(f1 - h1f), "f"(f0 - h0f));
}
__device__ __forceinline__ float gelu(float v){
    return 0.5f * v * (1.0f + erff(v * 0.70710678118654752440f));
}
__device__ __forceinline__ void ldsm4(uint32_t* r, uint32_t a){
    asm volatile("ldmatrix.sync.aligned.m8n8.x4.shared.b16 {%0,%1,%2,%3}, [%4];"
      : "=r"(r[0]), "=r"(r[1]), "=r"(r[2]), "=r"(r[3]) : "r"(a));
}
__device__ __forceinline__ void mmabf(float* c, const uint32_t* a, uint32_t b0, uint32_t b1){
    asm volatile("mma.sync.aligned.m16n8k16.row.col.f32.bf16.bf16.f32 "
      "{%0,%1,%2,%3},{%4,%5,%6,%7},{%8,%9},{%0,%1,%2,%3};"
      : "+f"(c[0]), "+f"(c[1]), "+f"(c[2]), "+f"(c[3])
      : "r"(a[0]), "r"(a[1]), "r"(a[2]), "r"(a[3]), "r"(b0), "r"(b1));
}
#define CP16(d,s)  asm volatile("cp.async.cg.shared.global [%0], [%1], 16;" :: "r"(d), "l"(s) : "memory")
#define CPCOMMIT() asm volatile("cp.async.commit_group;" ::: "memory")
#define CPWAIT0()  asm volatile("cp.async.wait_group 0;" ::: "memory")
#define CPWAIT1()  asm volatile("cp.async.wait_group 1;" ::: "memory")

struct Frag { uint32_t offA, mA, offB, mB, ksel; };

__device__ __forceinline__ Frag mk_frag(int lane, int wm, int wn){
    Frag f;
    uint32_t rA = wm * 64 + (lane & 7) + ((lane >> 3) & 1) * 8;
    uint32_t rB = wn * 32 + (lane & 7) + ((lane >> 3) & 1) * 8;
    f.ksel = ((lane >> 4) & 1) * 16;
    f.mA = ((rA >> 1) & 3) << 4;  f.mB = ((rB >> 1) & 3) << 4;
    f.offA = rA * 64;             f.offB = rB * 64;
    return f;
}

// one K=32 tile, 64B rows. A: aB hi, aB+8192 lo; B: bB hi, bB+8192 lo.
__device__ __forceinline__ void mma32(uint32_t aB, uint32_t bB, const Frag& f, float c[4][4][4])
{
#pragma unroll
    for (int ks = 0; ks < 2; ks++){
        uint32_t ka = ks * 32 + f.ksel;
        uint32_t ao = f.offA + (ka ^ f.mA);
        uint32_t bo = f.offB + (ka ^ f.mB);
        uint32_t ah[4][4], al[4][4], bh[2][4], bl[2][4];
#pragma unroll
        for (int i = 0; i < 4; i++){ ldsm4(ah[i], aB + ao + i*1024u); ldsm4(al[i], aB + 8192u + ao + i*1024u); }
#pragma unroll
        for (int j = 0; j < 2; j++){ ldsm4(bh[j], bB + bo + j*1024u); ldsm4(bl[j], bB + 8192u + bo + j*1024u); }
#pragma unroll
        for (int i = 0; i < 4; i++)
#pragma unroll
        for (int jt = 0; jt < 4; jt++){
            int j = jt >> 1, s2 = jt & 1;
            mmabf(c[i][jt], ah[i], bh[j][s2], bh[j][s2+2]);
            mmabf(c[i][jt], ah[i], bl[j][s2], bl[j][s2+2]);
            mmabf(c[i][jt], al[i], bh[j][s2], bh[j][s2+2]);
        }
    }
}

// convert one W fp32 tile (smem, [32k][128n] rows of 512B) -> bf16 hi/lo planes
__device__ __forceinline__ void convW(const float* wf, char* bB, int nB, int khB){
    float fB[16];
#pragma unroll
    for (int l = 0; l < 16; l++) fB[l] = wf[(khB * 16 + l) * 128 + nB];
    char* Bh = bB; char* Bl = bB + 8192;
#pragma unroll
    for (int l = 0; l < 16; l += 4){
        uint32_t hp0, lp0, hp1, lp1;
        split2(fB[l],   fB[l+1], hp0, lp0);
        split2(fB[l+2], fB[l+3], hp1, lp1);
        uint32_t off = sw64((uint32_t)nB * 64 + khB * 32 + l * 2);
        *(uint2*)(Bh + off) = make_uint2(hp0, hp1);
        *(uint2*)(Bl + off) = make_uint2(lp0, lp1);
    }
}

// ============ k0: x -> pre-swizzled bf16 hi/lo image (once) ============
__global__ void k0(const float* __restrict__ x)
{
    int tid = threadIdx.x;           // 256
    int m = tid >> 1, h = tid & 1;
    const float4* xr = (const float4*)(x + m * 128 + h * 64);
#pragma unroll
    for (int j4 = 0; j4 < 16; j4++){
        float4 v = xr[j4];
        int l = j4 * 4;
        int slot = h * 2 + (l >> 5);
        int kk = l & 31;
        uint32_t hp0, lp0, hp1, lp1;
        split2(v.x, v.y, hp0, lp0);
        split2(v.z, v.w, hp1, lp1);
        uint32_t off = sw64((uint32_t)m * 64 + kk * 2);
        *(uint2*)(g_ximg + slot * 16384 + off) = make_uint2(hp0, hp1);
        *(uint2*)(g_ximg + slot * 16384 + 8192 + off) = make_uint2(lp0, lp1);
    }
}

// ============ k1: h1 = gelu(x @ W1 + b1) -> h1 slot image ============
// grid (4, 1000). 256 threads, 2 CTAs/SM.
__global__ void __launch_bounds__(256, 2)
k1(const float* __restrict__ W1, const float* __restrict__ b1)
{
    extern __shared__ char sm[];
    uint32_t sb = smem_u32(sm);
    const int nc = blockIdx.x, g = blockIdx.y;
    const int tid = threadIdx.x, lane = tid & 31, w = tid >> 5;
    const int wm = w & 1, wn = w >> 1;
    const int nB = tid & 127, khB = tid >> 7;

    const float* Wg = W1 + (size_t)g * 65536 + nc * 128;

    // prologue: cp A image (64KB) + W tile 0 (16KB fp32)
#pragma unroll
    for (int i = 0; i < 16; i++){
        uint32_t idx = tid + i * 256;
        CP16(sb + K1_A + idx * 16, g_ximg + idx * 16);
    }
#pragma unroll
    for (int i = 0; i < 4; i++){
        uint32_t idx = tid + i * 256, k = idx >> 5, n4 = idx & 31;
        CP16(sb + K1_WF + k * 512 + n4 * 16, Wg + (size_t)k * 512 + n4 * 4);
    }
    CPCOMMIT();

    float* b1s = (float*)sm;
    if (tid < 128) b1s[tid] = b1[(size_t)g * 512 + nc * 128 + tid];

    float c[4][4][4];
#pragma unroll
    for (int i = 0; i < 4; i++)
#pragma unroll
    for (int jt = 0; jt < 4; jt++)
#pragma unroll
    for (int q = 0; q < 4; q++) c[i][jt][q] = 0.0f;
    Frag f = mk_frag(lane, wm, wn);

#pragma unroll
    for (int kt = 0; kt < 4; kt++){
        CPWAIT0();
        __syncthreads();
        convW((const float*)(sm + K1_WF), sm + K1_B, nB, khB);
        __syncthreads();
        if (kt < 3){
#pragma unroll
            for (int i = 0; i < 4; i++){
                uint32_t idx = tid + i * 256, k = idx >> 5, n4 = idx & 31;
                CP16(sb + K1_WF + k * 512 + n4 * 16,
                     Wg + (size_t)(kt + 1) * 32 * 512 + (size_t)k * 512 + n4 * 4);
            }
            CPCOMMIT();
        }
        mma32(sb + K1_A + kt * 16384, sb + K1_B, f, c);
    }

    // epilogue: bias + gelu + split -> h1 slot image
    size_t gbase = (size_t)g * 262144;
#pragma unroll
    for (int i = 0; i < 4; i++)
#pragma unroll
    for (int jt = 0; jt < 4; jt++){
        int nl = wn * 32 + jt * 8 + 2 * (lane & 3);
        int r0 = wm * 64 + i * 16 + (lane >> 2);
        int C = nc * 128 + nl;
        int slot = C >> 5, kk = C & 31;
        float bb0 = b1s[nl], bb1 = b1s[nl + 1];
        uint32_t hp, lp;
        float v0 = gelu(c[i][jt][0] + bb0);
        float v1 = gelu(c[i][jt][1] + bb1);
        split2(v0, v1, hp, lp);
        char* p = g_h1img + gbase + (size_t)slot * 16384 + sw64((uint32_t)r0 * 64 + kk * 2);
        *(uint32_t*)p = hp; *(uint32_t*)(p + 8192) = lp;
        v0 = gelu(c[i][jt][2] + bb0);
        v1 = gelu(c[i][jt][3] + bb1);
        split2(v0, v1, hp, lp);
        p = g_h1img + gbase + (size_t)slot * 16384 + sw64((uint32_t)(r0 + 8) * 64 + kk * 2);
        *(uint32_t*)p = hp; *(uint32_t*)(p + 8192) = lp;
    }
}

// ============ k2: partial = sum_n gelu(h1 @ W2 + b2) * W3 ============
// grid (4, 1000). 256 threads, 2 CTAs/SM. 16 K32 tiles; A ring depth 3, B/Wf32 depth 2.
__global__ void __launch_bounds__(256, 2)
k2(const float* __restrict__ W2, const float* __restrict__ b2, const float* __restrict__ W3)
{
    extern __shared__ char sm[];
    uint32_t sb = smem_u32(sm);
    const int nc = blockIdx.x, g = blockIdx.y;
    const int tid = threadIdx.x, lane = tid & 31, w = tid >> 5;
    const int wm = w & 1, wn = w >> 1;
    const int nB = tid & 127, khB = tid >> 7;

    const char* h1g = g_h1img + (size_t)g * 262144;
    const float* Wg = W2 + (size_t)g * 262144 + nc * 128;

    auto cpA = [&](int kt, int s){
        const char* src = h1g + (size_t)kt * 16384;
        uint32_t dst = sb + K2_A + s * 16384;
#pragma unroll
        for (int i = 0; i < 4; i++){
            uint32_t idx = tid + i * 256;
            CP16(dst + idx * 16, src + idx * 16);
        }
    };
    auto cpW = [&](int kt, int s){
        uint32_t dst = sb + K2_WF + s * 16384;
        const float* src = Wg + (size_t)kt * 32 * 512;
#pragma unroll
        for (int i = 0; i < 4; i++){
            uint32_t idx = tid + i * 256, k = idx >> 5, n4 = idx & 31;
            CP16(dst + k * 512 + n4 * 16, src + (size_t)k * 512 + n4 * 4);
        }
    };

    // prologue
    cpA(0, 0); cpW(0, 0); CPCOMMIT();
    cpA(1, 1); cpW(1, 1); CPCOMMIT();

    float* b2s = (float*)sm;
    float* w3s = (float*)(sm + 512);
    if (tid < 128){
        b2s[tid] = b2[(size_t)g * 512 + nc * 128 + tid];
        w3s[tid] = W3[(size_t)g * 512 + nc * 128 + tid];
    }

    float c[4][4][4];
#pragma unroll
    for (int i = 0; i < 4; i++)
#pragma unroll
    for (int jt = 0; jt < 4; jt++)
#pragma unroll
    for (int q = 0; q < 4; q++) c[i][jt][q] = 0.0f;
    Frag f = mk_frag(lane, wm, wn);

    for (int kt = 0; kt < 16; kt++){
        if (kt >= 14) CPWAIT0(); else CPWAIT1();
        __syncthreads();
        convW((const float*)(sm + K2_WF + (kt & 1) * 16384),
              sm + K2_B + (kt & 1) * 16384, nB, khB);
        __syncthreads();
        if (kt < 14){
            cpA(kt + 2, (kt + 2) % 3);
            cpW(kt + 2, kt & 1);
            CPCOMMIT();
        }
        mma32(sb + K2_A + (kt % 3) * 16384, sb + K2_B + (kt & 1) * 16384, f, c);
    }
    __syncthreads();

    // epilogue: bias + gelu + W3-dot; shuffle + smem reduce (red overlays A ring)
    float* red = (float*)(sm + K2_A);
#pragma unroll
    for (int i = 0; i < 4; i++){
        float s0 = 0.0f, s1 = 0.0f;
#pragma unroll
        for (int jt = 0; jt < 4; jt++){
            int nl = wn * 32 + jt * 8 + 2 * (lane & 3);
            float bb0 = b2s[nl], bb1 = b2s[nl+1], ww0 = w3s[nl], ww1 = w3s[nl+1];
            s0 += gelu(c[i][jt][0] + bb0) * ww0 + gelu(c[i][jt][1] + bb1) * ww1;
            s1 += gelu(c[i][jt][2] + bb0) * ww0 + gelu(c[i][jt][3] + bb1) * ww1;
        }
        s0 += __shfl_xor_sync(0xFFFFFFFFu, s0, 1);
        s0 += __shfl_xor_sync(0xFFFFFFFFu, s0, 2);
        s1 += __shfl_xor_sync(0xFFFFFFFFu, s1, 1);
        s1 += __shfl_xor_sync(0xFFFFFFFFu, s1, 2);
        if ((lane & 3) == 0){
            int r0 = wm * 64 + i * 16 + (lane >> 2);
            red[r0 * 4 + wn] = s0;
            red[(r0 + 8) * 4 + wn] = s1;
        }
    }
    __syncthreads();
    if (tid < 128){
        const float* rr = red + tid * 4;
        g_part[((size_t)g * 4 + nc) * 128 + tid] = (rr[0] + rr[1]) + (rr[2] + rr[3]);
    }
}

// ============ k3 ============
__global__ void k3(const float* __restrict__ b3, float* __restrict__ out)
{
    int idx = blockIdx.x * 256 + threadIdx.x;
    if (idx >= 128 * NG) return;
    int m = idx / NG;
    int g = idx - m * NG;
    const float* p = g_part + (size_t)g * 512 + m;
    out[idx] = b3[g] + ((p[0] + p[128]) + (p[256] + p[384]));
}

extern "C" void kernel_launch(void* const* d_in, const int* in_sizes, int n_in,
                              void* d_out, int out_size)
{
    const float* x  = (const float*)d_in[0];
    const float* W1 = (const float*)d_in[1];
    const float* b1 = (const float*)d_in[2];
    const float* W2 = (const float*)d_in[3];
    const float* b2 = (const float*)d_in[4];
    const float* W3 = (const float*)d_in[5];
    const float* b3 = (const float*)d_in[6];
    float* out = (float*)d_out;

    cudaFuncSetAttribute(k1, cudaFuncAttributeMaxDynamicSharedMemorySize, SM1_BYTES);
    cudaFuncSetAttribute(k2, cudaFuncAttributeMaxDynamicSharedMemorySize, SM2_BYTES);

    k0<<<1, 256>>>(x);
    dim3 grid(4, NG);
    k1<<<grid, 256, SM1_BYTES>>>(W1, b1);
    k2<<<grid, 256, SM2_BYTES>>>(W2, b2, W3);
    k3<<<(128 * NG + 255) / 256, 256>>>(b3, out);
}